// round 3
// baseline (speedup 1.0000x reference)
#include <cuda_runtime.h>

#define NN 50000
#define NE 800000
#define FF 128
#define FQ 32                      // float4s per feature row
#define NG 64
#define NC 16
#define SCAN_B 512
#define NBLK ((NN + SCAN_B - 1) / SCAN_B)   // 98

// ---------------- scratch (static device globals; no allocation) ----------------
__device__ int    g_is64;
__device__ int    g_counts[NN];
__device__ int    g_fill[NN];
__device__ int    g_rowptr[NN + 1];
__device__ int    g_col[NE];
__device__ float  g_dinv[NN];
__device__ float4 g_bufA[NN * FQ];   // GEMM output (dinv-scaled)
__device__ float4 g_bufB[NN * FQ];   // layer input / agg output
__device__ float  g_pool[NG * FF];
__device__ int    g_bsum[NBLK];

// dtype-agnostic index load (edge_index / batch may be int32 or int64)
__device__ __forceinline__ int load_idx(const void* p, long long i, int is64) {
    if (is64) return (int)((const long long*)p)[i];
    return ((const int*)p)[i];
}

// ---------------- dtype detection ----------------
__global__ void k_detect(const int* __restrict__ w32) {
    // int64 small values => odd words (high halves) all zero.
    int nz = 0;
    #pragma unroll
    for (int k = 0; k < 16; k++) nz |= w32[2 * k + 1];
    g_is64 = (nz == 0) ? 1 : 0;
}

// ---------------- CSR build ----------------
__global__ void k_zero() {
    int i = blockIdx.x * blockDim.x + threadIdx.x;
    if (i < NN) { g_counts[i] = 0; g_fill[i] = 0; }
}

__global__ void k_count(const void* __restrict__ ei) {
    int i = blockIdx.x * blockDim.x + threadIdx.x;
    if (i >= NE) return;
    int is64 = g_is64;
    int d = load_idx(ei, (long long)NE + i, is64);
    atomicAdd(&g_counts[d], 1);
}

// block-wide inclusive scan via shuffles; writes exclusive partials + block sums
__global__ void k_scan1() {
    __shared__ int warp_sums[SCAN_B / 32];
    int i = blockIdx.x * SCAN_B + threadIdx.x;
    int v = (i < NN) ? g_counts[i] : 0;
    int lane = threadIdx.x & 31;
    int wid  = threadIdx.x >> 5;

    int x = v;
    #pragma unroll
    for (int off = 1; off < 32; off <<= 1) {
        int t = __shfl_up_sync(0xffffffffu, x, off);
        if (lane >= off) x += t;
    }
    if (lane == 31) warp_sums[wid] = x;
    __syncthreads();
    if (wid == 0) {
        int w = (lane < SCAN_B / 32) ? warp_sums[lane] : 0;
        #pragma unroll
        for (int off = 1; off < SCAN_B / 32; off <<= 1) {
            int t = __shfl_up_sync(0xffffffffu, w, off);
            if (lane >= off) w += t;
        }
        if (lane < SCAN_B / 32) warp_sums[lane] = w;
    }
    __syncthreads();
    int base = (wid > 0) ? warp_sums[wid - 1] : 0;
    int incl = base + x;
    if (i < NN) g_rowptr[i] = incl - v;            // exclusive within block
    if (threadIdx.x == SCAN_B - 1) g_bsum[blockIdx.x] = incl;
}

__global__ void k_scan2() {
    int run = 0;
    for (int b = 0; b < NBLK; b++) { int t = g_bsum[b]; g_bsum[b] = run; run += t; }
}

__global__ void k_scan3() {
    int i = blockIdx.x * SCAN_B + threadIdx.x;
    if (i < NN) {
        g_rowptr[i] += g_bsum[blockIdx.x];
        g_dinv[i] = rsqrtf((float)(g_counts[i] + 1));   // +1 = self loop
    }
    if (i == 0) g_rowptr[NN] = NE;
}

__global__ void k_fill(const void* __restrict__ ei) {
    int i = blockIdx.x * blockDim.x + threadIdx.x;
    if (i >= NE) return;
    int is64 = g_is64;
    int s = load_idx(ei, (long long)i, is64);
    int d = load_idx(ei, (long long)NE + i, is64);
    int pos = g_rowptr[d] + atomicAdd(&g_fill[d], 1);
    g_col[pos] = s;
}

// ---------------- copy x -> g_bufB ----------------
__global__ void k_copy(const float4* __restrict__ x4) {
    int i = blockIdx.x * blockDim.x + threadIdx.x;
    if (i < NN * FQ) g_bufB[i] = x4[i];
}

// ---------------- GEMM: g_bufA[r] = (g_bufB[r] @ W) * dinv[r] ----------------
// BM=64 rows/block, all 128 cols, BK=32, 256 threads, 8x4 microtile.
__global__ void __launch_bounds__(256) k_gemm(const float* __restrict__ W) {
    __shared__ float  Xs[64 * 32];
    __shared__ float4 Ws[32 * 32];        // [k][colquad]

    int tid = threadIdx.x;
    int tr = tid >> 5;                    // 0..7  row group
    int tc = tid & 31;                    // 0..31 col quad
    int rowBase = blockIdx.x * 64;

    float acc[8][4];
    #pragma unroll
    for (int r = 0; r < 8; r++)
        #pragma unroll
        for (int j = 0; j < 4; j++) acc[r][j] = 0.f;

    for (int k0 = 0; k0 < FF; k0 += 32) {
        int k0q = k0 >> 2;                // float4 offset
        #pragma unroll
        for (int t = 0; t < 2; t++) {
            int idx = tid + t * 256;      // 512 float4 loads (64x32 floats)
            int r   = idx >> 3;
            int kq  = idx & 7;
            int grow = rowBase + r;
            float4 v = make_float4(0.f, 0.f, 0.f, 0.f);
            if (grow < NN) v = g_bufB[grow * FQ + k0q + kq];
            *(float4*)&Xs[r * 32 + kq * 4] = v;
        }
        #pragma unroll
        for (int t = 0; t < 4; t++) {
            int idx = tid + t * 256;      // 1024 float4 (32x128 floats)
            int k   = idx >> 5;
            int cq  = idx & 31;
            Ws[k * 32 + cq] = *(const float4*)&W[(k0 + k) * FF + cq * 4];
        }
        __syncthreads();

        #pragma unroll
        for (int k = 0; k < 32; k++) {
            float4 w = Ws[k * 32 + tc];
            #pragma unroll
            for (int r = 0; r < 8; r++) {
                float x = Xs[(tr * 8 + r) * 32 + k];
                acc[r][0] += x * w.x;
                acc[r][1] += x * w.y;
                acc[r][2] += x * w.z;
                acc[r][3] += x * w.w;
            }
        }
        __syncthreads();
    }

    #pragma unroll
    for (int r = 0; r < 8; r++) {
        int grow = rowBase + tr * 8 + r;
        if (grow < NN) {
            float dv = g_dinv[grow];
            g_bufA[grow * FQ + tc] = make_float4(acc[r][0] * dv, acc[r][1] * dv,
                                                 acc[r][2] * dv, acc[r][3] * dv);
        }
    }
}

// ---------------- aggregation: bufB[v] = act( dinv[v]*(bufA[v] + sum_{u in N(v)} bufA[u]) + b ) ----
__global__ void __launch_bounds__(256) k_agg(const float* __restrict__ bias,
                                             int do_relu) {
    int v    = (blockIdx.x * blockDim.x + threadIdx.x) >> 5;  // one warp per node
    int lane = threadIdx.x & 31;
    if (v >= NN) return;

    float4 acc = g_bufA[v * FQ + lane];
    int s = g_rowptr[v];
    int e = g_rowptr[v + 1];
    for (int j = s; j < e; j++) {
        int u = g_col[j];
        float4 m = g_bufA[u * FQ + lane];
        acc.x += m.x; acc.y += m.y; acc.z += m.z; acc.w += m.w;
    }
    float  dv = g_dinv[v];
    float4 b  = *(const float4*)&bias[lane * 4];
    acc.x = acc.x * dv + b.x;
    acc.y = acc.y * dv + b.y;
    acc.z = acc.z * dv + b.z;
    acc.w = acc.w * dv + b.w;
    if (do_relu) {
        acc.x = fmaxf(acc.x, 0.f); acc.y = fmaxf(acc.y, 0.f);
        acc.z = fmaxf(acc.z, 0.f); acc.w = fmaxf(acc.w, 0.f);
    }
    g_bufB[v * FQ + lane] = acc;
}

// ---------------- mean pooling per graph (batch sorted); reads g_bufB ----------------
__device__ __forceinline__ int lower_bound_idx(const void* a, int val, int is64) {
    int lo = 0, hi = NN;
    while (lo < hi) {
        int mid = (lo + hi) >> 1;
        if (load_idx(a, mid, is64) < val) lo = mid + 1; else hi = mid;
    }
    return lo;
}

__global__ void k_pool(const void* __restrict__ batch) {
    __shared__ int se[2];
    int g = blockIdx.x;
    if (threadIdx.x == 0) {
        int is64 = g_is64;
        se[0] = lower_bound_idx(batch, g, is64);
        se[1] = lower_bound_idx(batch, g + 1, is64);
    }
    __syncthreads();
    int s = se[0], e = se[1];
    const float* h = (const float*)g_bufB;
    float sum = 0.f;
    for (int i = s; i < e; i++) sum += h[i * FF + threadIdx.x];
    float cnt = (float)(e - s);
    g_pool[g * FF + threadIdx.x] = sum / fmaxf(cnt, 1.0f);
}

// ---------------- classifier: out[g,c] = pooled[g] . Wc[:,c] + bc[c] ----------------
__global__ void k_cls(const float* __restrict__ Wc,
                      const float* __restrict__ bc,
                      float* __restrict__ out) {
    int tid = threadIdx.x;             // 1024 threads
    int g = tid >> 4;
    int c = tid & 15;
    float sum = bc[c];
    #pragma unroll 8
    for (int k = 0; k < FF; k++)
        sum += g_pool[g * FF + k] * Wc[k * NC + c];
    out[g * NC + c] = sum;
}

// ---------------- launch ----------------
extern "C" void kernel_launch(void* const* d_in, const int* in_sizes, int n_in,
                              void* d_out, int out_size) {
    const float* x  = (const float*)d_in[0];
    const void*  ei = d_in[1];
    const void*  batch = d_in[2];
    const float* W0 = (const float*)d_in[3];
    const float* b0 = (const float*)d_in[4];
    const float* W1 = (const float*)d_in[5];
    const float* b1 = (const float*)d_in[6];
    const float* W2 = (const float*)d_in[7];
    const float* b2 = (const float*)d_in[8];
    const float* Wc = (const float*)d_in[9];
    const float* bc = (const float*)d_in[10];
    float* out = (float*)d_out;

    // dtype detect + CSR build + dinv
    k_detect<<<1, 1>>>((const int*)ei);
    k_zero  <<<(NN + 255) / 256, 256>>>();
    k_count <<<(NE + 255) / 256, 256>>>(ei);
    k_scan1 <<<NBLK, SCAN_B>>>();
    k_scan2 <<<1, 1>>>();
    k_scan3 <<<NBLK, SCAN_B>>>();
    k_fill  <<<(NE + 255) / 256, 256>>>(ei);

    // stage input
    k_copy<<<(NN * FQ + 255) / 256, 256>>>((const float4*)x);

    const int gemm_grid = (NN + 63) / 64;
    const int agg_grid  = (NN + 7) / 8;

    k_gemm<<<gemm_grid, 256>>>(W0);
    k_agg <<<agg_grid,  256>>>(b0, 1);
    k_gemm<<<gemm_grid, 256>>>(W1);
    k_agg <<<agg_grid,  256>>>(b1, 1);
    k_gemm<<<gemm_grid, 256>>>(W2);
    k_agg <<<agg_grid,  256>>>(b2, 0);

    k_pool<<<NG, FF>>>(batch);
    k_cls <<<1, 1024>>>(Wc, bc, out);
}

// round 4
// speedup vs baseline: 1.0417x; 1.0417x over previous
#include <cuda_runtime.h>
#include <mma.h>

using namespace nvcuda;

#define NN 50000
#define NE 800000
#define FF 128
#define FQ 32                      // float4s per feature row
#define NG 64
#define NC 16
#define SCAN_B 512
#define NBLK ((NN + SCAN_B - 1) / SCAN_B)   // 98

// GEMM tiling
#define BM 64
#define LDA 40                     // 32 + 8 skew
#define LDW 136                    // 128 + 8 skew
#define SMEM_FLOATS 8704           // max(64*40 + 32*136, 64*136) = 8704

// ---------------- scratch (static device globals; no allocation) ----------------
__device__ int    g_is64;
__device__ int    g_counts[NN];
__device__ int    g_fill[NN];
__device__ int    g_rowptr[NN + 1];
__device__ int    g_col[NE];
__device__ float  g_dinv[NN];
__device__ float4 g_bufA[NN * FQ];   // GEMM output (dinv-scaled messages)
__device__ float4 g_bufB[NN * FQ];   // layer input / agg output
__device__ float  g_pool[NG * FF];
__device__ int    g_bsum[NBLK];

// dtype-agnostic index load (edge_index / batch may be int32 or int64)
__device__ __forceinline__ int load_idx(const void* p, long long i, int is64) {
    if (is64) return (int)((const long long*)p)[i];
    return ((const int*)p)[i];
}

// ---------------- init: zero counts + dtype detect ----------------
__global__ void k_init(const int* __restrict__ w32) {
    int i = blockIdx.x * blockDim.x + threadIdx.x;
    if (i < NN) { g_counts[i] = 0; g_fill[i] = 0; }
    if (i == 0) {
        // int64 small values => odd 32-bit words (high halves) all zero.
        int nz = 0;
        #pragma unroll
        for (int k = 0; k < 16; k++) nz |= w32[2 * k + 1];
        g_is64 = (nz == 0) ? 1 : 0;
    }
}

__global__ void k_count(const void* __restrict__ ei) {
    int i = blockIdx.x * blockDim.x + threadIdx.x;
    if (i >= NE) return;
    int d = load_idx(ei, (long long)NE + i, g_is64);
    atomicAdd(&g_counts[d], 1);
}

// block-wide inclusive scan via shuffles; writes exclusive partials + block sums
__global__ void k_scan1() {
    __shared__ int warp_sums[SCAN_B / 32];
    int i = blockIdx.x * SCAN_B + threadIdx.x;
    int v = (i < NN) ? g_counts[i] : 0;
    int lane = threadIdx.x & 31;
    int wid  = threadIdx.x >> 5;

    int x = v;
    #pragma unroll
    for (int off = 1; off < 32; off <<= 1) {
        int t = __shfl_up_sync(0xffffffffu, x, off);
        if (lane >= off) x += t;
    }
    if (lane == 31) warp_sums[wid] = x;
    __syncthreads();
    if (wid == 0) {
        int w = (lane < SCAN_B / 32) ? warp_sums[lane] : 0;
        #pragma unroll
        for (int off = 1; off < SCAN_B / 32; off <<= 1) {
            int t = __shfl_up_sync(0xffffffffu, w, off);
            if (lane >= off) w += t;
        }
        if (lane < SCAN_B / 32) warp_sums[lane] = w;
    }
    __syncthreads();
    int base = (wid > 0) ? warp_sums[wid - 1] : 0;
    int incl = base + x;
    if (i < NN) g_rowptr[i] = incl - v;            // exclusive within block
    if (threadIdx.x == SCAN_B - 1) g_bsum[blockIdx.x] = incl;
}

__global__ void k_scan2() {
    int run = 0;
    for (int b = 0; b < NBLK; b++) { int t = g_bsum[b]; g_bsum[b] = run; run += t; }
}

__global__ void k_scan3() {
    int i = blockIdx.x * SCAN_B + threadIdx.x;
    if (i < NN) {
        g_rowptr[i] += g_bsum[blockIdx.x];
        g_dinv[i] = rsqrtf((float)(g_counts[i] + 1));   // +1 = self loop
    }
    if (i == 0) g_rowptr[NN] = NE;
}

__global__ void k_fill(const void* __restrict__ ei) {
    int i = blockIdx.x * blockDim.x + threadIdx.x;
    if (i >= NE) return;
    int is64 = g_is64;
    int s = load_idx(ei, (long long)i, is64);
    int d = load_idx(ei, (long long)NE + i, is64);
    int pos = g_rowptr[d] + atomicAdd(&g_fill[d], 1);
    g_col[pos] = s;
}

// ---------------- GEMM (tf32 tensor cores): g_bufA[r] = (src[r] @ W) * dinv[r] ----------------
// src: external x (srcSel==0) or g_bufB. BM=64 rows/block, 128 cols, 8 warps.
// Warp w: rows [ (w>>1)*16, +16 ), cols [ (w&1)*64, +64 ) via 4x m16n16k8 tf32 frags.
__global__ void __launch_bounds__(256) k_gemm(const float* __restrict__ xext,
                                              int srcSel,
                                              const float* __restrict__ W) {
    __shared__ float sm[SMEM_FLOATS];
    float* As = sm;               // 64 x LDA (32 K-cols + skew)
    float* Ws = sm + BM * LDA;    // 32 x LDW (128 N-cols + skew)

    const bool useX = (srcSel == 0);
    int tid = threadIdx.x;
    int wid = tid >> 5;
    int stripe = wid >> 1;        // 0..3 (16-row stripe)
    int half   = wid & 1;         // 0..1 (64-col half)
    int rowBase = blockIdx.x * BM;

    wmma::fragment<wmma::accumulator, 16, 16, 8, float> acc[4];
    #pragma unroll
    for (int c = 0; c < 4; c++) wmma::fill_fragment(acc[c], 0.0f);

    for (int kc = 0; kc < 4; kc++) {              // K chunks of 32
        // A tile: 64x32 floats = 512 float4, 2 per thread
        #pragma unroll
        for (int t = 0; t < 2; t++) {
            int idx = tid + t * 256;
            int r   = idx >> 3;
            int kq  = idx & 7;
            int grow = rowBase + r;
            float4 v = make_float4(0.f, 0.f, 0.f, 0.f);
            if (grow < NN) {
                if (useX) v = *(const float4*)&xext[(long long)grow * FF + kc * 32 + kq * 4];
                else      v = g_bufB[grow * FQ + kc * 8 + kq];
            }
            float* dst = &As[r * LDA + kq * 4];
            dst[0] = wmma::__float_to_tf32(v.x);
            dst[1] = wmma::__float_to_tf32(v.y);
            dst[2] = wmma::__float_to_tf32(v.z);
            dst[3] = wmma::__float_to_tf32(v.w);
        }
        // W chunk: 32x128 floats = 1024 float4, 4 per thread
        #pragma unroll
        for (int t = 0; t < 4; t++) {
            int idx = tid + t * 256;
            int k   = idx >> 5;
            int cq  = idx & 31;
            float4 v = *(const float4*)&W[(kc * 32 + k) * FF + cq * 4];
            float* dst = &Ws[k * LDW + cq * 4];
            dst[0] = wmma::__float_to_tf32(v.x);
            dst[1] = wmma::__float_to_tf32(v.y);
            dst[2] = wmma::__float_to_tf32(v.z);
            dst[3] = wmma::__float_to_tf32(v.w);
        }
        __syncthreads();

        #pragma unroll
        for (int kk = 0; kk < 4; kk++) {          // K steps of 8
            wmma::fragment<wmma::matrix_a, 16, 16, 8, wmma::precision::tf32, wmma::row_major> a;
            wmma::load_matrix_sync(a, &As[stripe * 16 * LDA + kk * 8], LDA);
            #pragma unroll
            for (int c = 0; c < 4; c++) {
                wmma::fragment<wmma::matrix_b, 16, 16, 8, wmma::precision::tf32, wmma::row_major> b;
                wmma::load_matrix_sync(b, &Ws[kk * 8 * LDW + half * 64 + c * 16], LDW);
                wmma::mma_sync(acc[c], a, b, acc[c]);
            }
        }
        __syncthreads();
    }

    // epilogue: frags -> shared (reusing As/Ws space) -> dinv scale -> global
    float* Cs = sm;               // 64 x LDW
    #pragma unroll
    for (int c = 0; c < 4; c++)
        wmma::store_matrix_sync(&Cs[(stripe * 16) * LDW + half * 64 + c * 16],
                                acc[c], LDW, wmma::mem_row_major);
    __syncthreads();

    #pragma unroll
    for (int t = 0; t < 8; t++) {
        int idx = tid + t * 256;          // 64 rows x 32 quads = 2048
        int r = idx >> 5;
        int q = idx & 31;
        int grow = rowBase + r;
        if (grow < NN) {
            float dv = g_dinv[grow];
            float4 v = *(float4*)&Cs[r * LDW + q * 4];
            g_bufA[grow * FQ + q] = make_float4(v.x * dv, v.y * dv, v.z * dv, v.w * dv);
        }
    }
}

// ---------------- aggregation: bufB[v] = act( dinv[v]*(bufA[v] + sum_{u in N(v)} bufA[u]) + b ) ----
__global__ void __launch_bounds__(256) k_agg(const float* __restrict__ bias,
                                             int do_relu) {
    int v    = (blockIdx.x * blockDim.x + threadIdx.x) >> 5;  // one warp per node
    int lane = threadIdx.x & 31;
    if (v >= NN) return;

    float4 acc = g_bufA[v * FQ + lane];
    int s = g_rowptr[v];
    int e = g_rowptr[v + 1];
    for (int j = s; j < e; j++) {
        int u = g_col[j];
        float4 m = g_bufA[u * FQ + lane];
        acc.x += m.x; acc.y += m.y; acc.z += m.z; acc.w += m.w;
    }
    float  dv = g_dinv[v];
    float4 b  = *(const float4*)&bias[lane * 4];
    acc.x = acc.x * dv + b.x;
    acc.y = acc.y * dv + b.y;
    acc.z = acc.z * dv + b.z;
    acc.w = acc.w * dv + b.w;
    if (do_relu) {
        acc.x = fmaxf(acc.x, 0.f); acc.y = fmaxf(acc.y, 0.f);
        acc.z = fmaxf(acc.z, 0.f); acc.w = fmaxf(acc.w, 0.f);
    }
    g_bufB[v * FQ + lane] = acc;
}

// ---------------- mean pooling per graph (batch sorted); reads g_bufB ----------------
__device__ __forceinline__ int lower_bound_idx(const void* a, int val, int is64) {
    int lo = 0, hi = NN;
    while (lo < hi) {
        int mid = (lo + hi) >> 1;
        if (load_idx(a, mid, is64) < val) lo = mid + 1; else hi = mid;
    }
    return lo;
}

__global__ void k_pool(const void* __restrict__ batch) {
    __shared__ int se[2];
    int g = blockIdx.x;
    if (threadIdx.x == 0) {
        int is64 = g_is64;
        se[0] = lower_bound_idx(batch, g, is64);
        se[1] = lower_bound_idx(batch, g + 1, is64);
    }
    __syncthreads();
    int s = se[0], e = se[1];
    const float* h = (const float*)g_bufB;
    float sum = 0.f;
    for (int i = s; i < e; i++) sum += h[i * FF + threadIdx.x];
    float cnt = (float)(e - s);
    g_pool[g * FF + threadIdx.x] = sum / fmaxf(cnt, 1.0f);
}

// ---------------- classifier: out[g,c] = pooled[g] . Wc[:,c] + bc[c] ----------------
__global__ void k_cls(const float* __restrict__ Wc,
                      const float* __restrict__ bc,
                      float* __restrict__ out) {
    int tid = threadIdx.x;             // 1024 threads
    int g = tid >> 4;
    int c = tid & 15;
    float sum = bc[c];
    #pragma unroll 8
    for (int k = 0; k < FF; k++)
        sum += g_pool[g * FF + k] * Wc[k * NC + c];
    out[g * NC + c] = sum;
}

// ---------------- launch ----------------
extern "C" void kernel_launch(void* const* d_in, const int* in_sizes, int n_in,
                              void* d_out, int out_size) {
    const float* x  = (const float*)d_in[0];
    const void*  ei = d_in[1];
    const void*  batch = d_in[2];
    const float* W0 = (const float*)d_in[3];
    const float* b0 = (const float*)d_in[4];
    const float* W1 = (const float*)d_in[5];
    const float* b1 = (const float*)d_in[6];
    const float* W2 = (const float*)d_in[7];
    const float* b2 = (const float*)d_in[8];
    const float* Wc = (const float*)d_in[9];
    const float* bc = (const float*)d_in[10];
    float* out = (float*)d_out;

    // init + CSR build + dinv
    k_init <<<(NN + 255) / 256, 256>>>((const int*)ei);
    k_count<<<(NE + 255) / 256, 256>>>(ei);
    k_scan1<<<NBLK, SCAN_B>>>();
    k_scan2<<<1, 1>>>();
    k_scan3<<<NBLK, SCAN_B>>>();
    k_fill <<<(NE + 255) / 256, 256>>>(ei);

    const int gemm_grid = (NN + BM - 1) / BM;
    const int agg_grid  = (NN + 7) / 8;

    k_gemm<<<gemm_grid, 256>>>(x, 0, W0);
    k_agg <<<agg_grid,  256>>>(b0, 1);
    k_gemm<<<gemm_grid, 256>>>(x, 1, W1);
    k_agg <<<agg_grid,  256>>>(b1, 1);
    k_gemm<<<gemm_grid, 256>>>(x, 1, W2);
    k_agg <<<agg_grid,  256>>>(b2, 0);

    k_pool<<<NG, FF>>>(batch);
    k_cls <<<1, 1024>>>(Wc, bc, out);
}

// round 6
// speedup vs baseline: 1.1531x; 1.1069x over previous
#include <cuda_runtime.h>
#include <cuda_fp16.h>
#include <mma.h>

using namespace nvcuda;

#define NN 50000
#define NE 800000
#define FF 128
#define FQ 32                      // float4s per feature row
#define MQ 32                      // uint2 (4 halves) per message row
#define NG 64
#define NC 16
#define SCAN_B 512
#define NBLK ((NN + SCAN_B - 1) / SCAN_B)   // 98

// GEMM tiling
#define BM 64
#define LDA 40                     // 32 + 8 skew
#define LDW 136                    // 128 + 8 skew
#define SMEM_FLOATS 8704           // max(64*40 + 32*136, 64*136) = 8704

// ---------------- scratch (static device globals; no allocation) ----------------
__device__ int    g_is64;
__device__ int    g_counts[NN];
__device__ int    g_fill[NN];
__device__ int    g_rowptr[NN + 1];
__device__ int    g_col[NE];
__device__ float  g_dinv[NN];
__device__ uint2  g_msg[NN * MQ];    // fp16 messages (dinv-scaled GEMM output)
__device__ float4 g_bufB[NN * FQ];   // layer input / agg output (fp32)
__device__ float  g_pool[NG * FF];
__device__ int    g_bsum[NBLK];

// bit reinterpretation helpers (no __half2_as_uint intrinsic in this toolkit)
__device__ __forceinline__ unsigned h2u(__half2 h) { return *reinterpret_cast<unsigned*>(&h); }
__device__ __forceinline__ __half2 u2h(unsigned u) { return *reinterpret_cast<__half2*>(&u); }

// dtype-agnostic index load (edge_index / batch may be int32 or int64)
__device__ __forceinline__ int load_idx(const void* p, long long i, int is64) {
    if (is64) return (int)((const long long*)p)[i];
    return ((const int*)p)[i];
}

// ---------------- init: zero counts + dtype detect ----------------
__global__ void k_init(const int* __restrict__ w32) {
    int i = blockIdx.x * blockDim.x + threadIdx.x;
    if (i < NN) { g_counts[i] = 0; g_fill[i] = 0; }
    if (i == 0) {
        int nz = 0;
        #pragma unroll
        for (int k = 0; k < 16; k++) nz |= w32[2 * k + 1];
        g_is64 = (nz == 0) ? 1 : 0;
    }
}

__global__ void k_count(const void* __restrict__ ei) {
    int i = blockIdx.x * blockDim.x + threadIdx.x;
    if (i >= NE) return;
    int d = load_idx(ei, (long long)NE + i, g_is64);
    atomicAdd(&g_counts[d], 1);
}

// block-wide inclusive scan via shuffles; writes exclusive partials + block sums
__global__ void k_scan1() {
    __shared__ int warp_sums[SCAN_B / 32];
    int i = blockIdx.x * SCAN_B + threadIdx.x;
    int v = (i < NN) ? g_counts[i] : 0;
    int lane = threadIdx.x & 31;
    int wid  = threadIdx.x >> 5;

    int x = v;
    #pragma unroll
    for (int off = 1; off < 32; off <<= 1) {
        int t = __shfl_up_sync(0xffffffffu, x, off);
        if (lane >= off) x += t;
    }
    if (lane == 31) warp_sums[wid] = x;
    __syncthreads();
    if (wid == 0) {
        int w = (lane < SCAN_B / 32) ? warp_sums[lane] : 0;
        #pragma unroll
        for (int off = 1; off < SCAN_B / 32; off <<= 1) {
            int t = __shfl_up_sync(0xffffffffu, w, off);
            if (lane >= off) w += t;
        }
        if (lane < SCAN_B / 32) warp_sums[lane] = w;
    }
    __syncthreads();
    int base = (wid > 0) ? warp_sums[wid - 1] : 0;
    int incl = base + x;
    if (i < NN) g_rowptr[i] = incl - v;            // exclusive within block
    if (threadIdx.x == SCAN_B - 1) g_bsum[blockIdx.x] = incl;
}

// exclusive scan of the 98 block sums, one block of 128 threads
__global__ void k_scan2() {
    __shared__ int ws[4];
    int lane = threadIdx.x & 31;
    int wid  = threadIdx.x >> 5;
    int v = (threadIdx.x < NBLK) ? g_bsum[threadIdx.x] : 0;
    int x = v;
    #pragma unroll
    for (int off = 1; off < 32; off <<= 1) {
        int t = __shfl_up_sync(0xffffffffu, x, off);
        if (lane >= off) x += t;
    }
    if (lane == 31) ws[wid] = x;
    __syncthreads();
    if (threadIdx.x == 0) {
        int run = 0;
        #pragma unroll
        for (int k = 0; k < 4; k++) { int t = ws[k]; ws[k] = run; run += t; }
    }
    __syncthreads();
    if (threadIdx.x < NBLK) g_bsum[threadIdx.x] = ws[wid] + x - v;  // exclusive
}

__global__ void k_scan3() {
    int i = blockIdx.x * SCAN_B + threadIdx.x;
    if (i < NN) {
        g_rowptr[i] += g_bsum[blockIdx.x];
        g_dinv[i] = rsqrtf((float)(g_counts[i] + 1));   // +1 = self loop
    }
    if (i == 0) g_rowptr[NN] = NE;
}

__global__ void k_fill(const void* __restrict__ ei) {
    int i = blockIdx.x * blockDim.x + threadIdx.x;
    if (i >= NE) return;
    int is64 = g_is64;
    int s = load_idx(ei, (long long)i, is64);
    int d = load_idx(ei, (long long)NE + i, is64);
    int pos = g_rowptr[d] + atomicAdd(&g_fill[d], 1);
    g_col[pos] = s;
}

// ---------------- GEMM (tf32): g_msg[r] = fp16( (src[r] @ W) * dinv[r] ) ----------------
__global__ void __launch_bounds__(256) k_gemm(const float* __restrict__ xext,
                                              int srcSel,
                                              const float* __restrict__ W) {
    __shared__ float sm[SMEM_FLOATS];
    float* As = sm;               // 64 x LDA
    float* Ws = sm + BM * LDA;    // 32 x LDW

    const bool useX = (srcSel == 0);
    int tid = threadIdx.x;
    int wid = tid >> 5;
    int stripe = wid >> 1;        // 0..3 (16-row stripe)
    int half   = wid & 1;         // 0..1 (64-col half)
    int rowBase = blockIdx.x * BM;

    wmma::fragment<wmma::accumulator, 16, 16, 8, float> acc[4];
    #pragma unroll
    for (int c = 0; c < 4; c++) wmma::fill_fragment(acc[c], 0.0f);

    for (int kc = 0; kc < 4; kc++) {              // K chunks of 32
        #pragma unroll
        for (int t = 0; t < 2; t++) {
            int idx = tid + t * 256;
            int r   = idx >> 3;
            int kq  = idx & 7;
            int grow = rowBase + r;
            float4 v = make_float4(0.f, 0.f, 0.f, 0.f);
            if (grow < NN) {
                if (useX) v = *(const float4*)&xext[(long long)grow * FF + kc * 32 + kq * 4];
                else      v = g_bufB[grow * FQ + kc * 8 + kq];
            }
            float* dst = &As[r * LDA + kq * 4];
            dst[0] = wmma::__float_to_tf32(v.x);
            dst[1] = wmma::__float_to_tf32(v.y);
            dst[2] = wmma::__float_to_tf32(v.z);
            dst[3] = wmma::__float_to_tf32(v.w);
        }
        #pragma unroll
        for (int t = 0; t < 4; t++) {
            int idx = tid + t * 256;
            int k   = idx >> 5;
            int cq  = idx & 31;
            float4 v = *(const float4*)&W[(kc * 32 + k) * FF + cq * 4];
            float* dst = &Ws[k * LDW + cq * 4];
            dst[0] = wmma::__float_to_tf32(v.x);
            dst[1] = wmma::__float_to_tf32(v.y);
            dst[2] = wmma::__float_to_tf32(v.z);
            dst[3] = wmma::__float_to_tf32(v.w);
        }
        __syncthreads();

        #pragma unroll
        for (int kk = 0; kk < 4; kk++) {
            wmma::fragment<wmma::matrix_a, 16, 16, 8, wmma::precision::tf32, wmma::row_major> a;
            wmma::load_matrix_sync(a, &As[stripe * 16 * LDA + kk * 8], LDA);
            #pragma unroll
            for (int c = 0; c < 4; c++) {
                wmma::fragment<wmma::matrix_b, 16, 16, 8, wmma::precision::tf32, wmma::row_major> b;
                wmma::load_matrix_sync(b, &Ws[kk * 8 * LDW + half * 64 + c * 16], LDW);
                wmma::mma_sync(acc[c], a, b, acc[c]);
            }
        }
        __syncthreads();
    }

    // epilogue: frags -> shared -> dinv scale -> fp16 -> global
    float* Cs = sm;               // 64 x LDW
    #pragma unroll
    for (int c = 0; c < 4; c++)
        wmma::store_matrix_sync(&Cs[(stripe * 16) * LDW + half * 64 + c * 16],
                                acc[c], LDW, wmma::mem_row_major);
    __syncthreads();

    #pragma unroll
    for (int t = 0; t < 8; t++) {
        int idx = tid + t * 256;          // 64 rows x 32 quads
        int r = idx >> 5;
        int q = idx & 31;
        int grow = rowBase + r;
        if (grow < NN) {
            float dv = g_dinv[grow];
            float4 v = *(float4*)&Cs[r * LDW + q * 4];
            __half2 h0 = __floats2half2_rn(v.x * dv, v.y * dv);
            __half2 h1 = __floats2half2_rn(v.z * dv, v.w * dv);
            uint2 u;
            u.x = h2u(h0);
            u.y = h2u(h1);
            g_msg[grow * MQ + q] = u;
        }
    }
}

// ---------------- aggregation: bufB[v] = act( dinv[v]*sum_{u in N(v)+v} msg[u] + b ) ----
__device__ __forceinline__ void acc_msg(float4& a, uint2 m) {
    float2 lo = __half22float2(u2h(m.x));
    float2 hi = __half22float2(u2h(m.y));
    a.x += lo.x; a.y += lo.y; a.z += hi.x; a.w += hi.y;
}

__global__ void __launch_bounds__(256) k_agg(const float* __restrict__ bias,
                                             int do_relu) {
    int v    = (blockIdx.x * blockDim.x + threadIdx.x) >> 5;  // one warp per node
    int lane = threadIdx.x & 31;
    if (v >= NN) return;

    float4 acc = make_float4(0.f, 0.f, 0.f, 0.f);
    acc_msg(acc, g_msg[v * MQ + lane]);                        // self loop

    int s = g_rowptr[v];
    int e = g_rowptr[v + 1];
    int j = s;
    for (; j + 1 < e; j += 2) {
        int u0 = g_col[j];
        int u1 = g_col[j + 1];
        uint2 m0 = g_msg[u0 * MQ + lane];
        uint2 m1 = g_msg[u1 * MQ + lane];
        acc_msg(acc, m0);
        acc_msg(acc, m1);
    }
    if (j < e) acc_msg(acc, g_msg[g_col[j] * MQ + lane]);

    float  dv = g_dinv[v];
    float4 b  = *(const float4*)&bias[lane * 4];
    acc.x = acc.x * dv + b.x;
    acc.y = acc.y * dv + b.y;
    acc.z = acc.z * dv + b.z;
    acc.w = acc.w * dv + b.w;
    if (do_relu) {
        acc.x = fmaxf(acc.x, 0.f); acc.y = fmaxf(acc.y, 0.f);
        acc.z = fmaxf(acc.z, 0.f); acc.w = fmaxf(acc.w, 0.f);
    }
    g_bufB[v * FQ + lane] = acc;
}

// ---------------- mean pooling per graph (batch sorted); reads g_bufB ----------------
__device__ __forceinline__ int lower_bound_idx(const void* a, int val, int is64) {
    int lo = 0, hi = NN;
    while (lo < hi) {
        int mid = (lo + hi) >> 1;
        if (load_idx(a, mid, is64) < val) lo = mid + 1; else hi = mid;
    }
    return lo;
}

__global__ void k_pool(const void* __restrict__ batch) {
    __shared__ int se[2];
    int g = blockIdx.x;
    if (threadIdx.x == 0) {
        int is64 = g_is64;
        se[0] = lower_bound_idx(batch, g, is64);
        se[1] = lower_bound_idx(batch, g + 1, is64);
    }
    __syncthreads();
    int s = se[0], e = se[1];
    const float* h = (const float*)g_bufB;
    float sum = 0.f;
    for (int i = s; i < e; i++) sum += h[i * FF + threadIdx.x];
    float cnt = (float)(e - s);
    g_pool[g * FF + threadIdx.x] = sum / fmaxf(cnt, 1.0f);
}

// ---------------- classifier ----------------
__global__ void k_cls(const float* __restrict__ Wc,
                      const float* __restrict__ bc,
                      float* __restrict__ out) {
    int tid = threadIdx.x;             // 1024 threads
    int g = tid >> 4;
    int c = tid & 15;
    float sum = bc[c];
    #pragma unroll 8
    for (int k = 0; k < FF; k++)
        sum += g_pool[g * FF + k] * Wc[k * NC + c];
    out[g * NC + c] = sum;
}

// ---------------- launch ----------------
extern "C" void kernel_launch(void* const* d_in, const int* in_sizes, int n_in,
                              void* d_out, int out_size) {
    const float* x  = (const float*)d_in[0];
    const void*  ei = d_in[1];
    const void*  batch = d_in[2];
    const float* W0 = (const float*)d_in[3];
    const float* b0 = (const float*)d_in[4];
    const float* W1 = (const float*)d_in[5];
    const float* b1 = (const float*)d_in[6];
    const float* W2 = (const float*)d_in[7];
    const float* b2 = (const float*)d_in[8];
    const float* Wc = (const float*)d_in[9];
    const float* bc = (const float*)d_in[10];
    float* out = (float*)d_out;

    k_init <<<(NN + 255) / 256, 256>>>((const int*)ei);
    k_count<<<(NE + 255) / 256, 256>>>(ei);
    k_scan1<<<NBLK, SCAN_B>>>();
    k_scan2<<<1, 128>>>();
    k_scan3<<<NBLK, SCAN_B>>>();
    k_fill <<<(NE + 255) / 256, 256>>>(ei);

    const int gemm_grid = (NN + BM - 1) / BM;
    const int agg_grid  = (NN + 7) / 8;

    k_gemm<<<gemm_grid, 256>>>(x, 0, W0);
    k_agg <<<agg_grid,  256>>>(b0, 1);
    k_gemm<<<gemm_grid, 256>>>(x, 1, W1);
    k_agg <<<agg_grid,  256>>>(b1, 1);
    k_gemm<<<gemm_grid, 256>>>(x, 1, W2);
    k_agg <<<agg_grid,  256>>>(b2, 0);

    k_pool<<<NG, FF>>>(batch);
    k_cls <<<1, 1024>>>(Wc, bc, out);
}

// round 7
// speedup vs baseline: 1.2399x; 1.0753x over previous
#include <cuda_runtime.h>
#include <cuda_fp16.h>
#include <mma.h>

using namespace nvcuda;

#define NN 50000
#define NE 800000
#define FF 128
#define FQ 32                      // float4s per feature row
#define MQ 32                      // uint2 (4 halves) per message row
#define NG 64
#define NC 16
#define SCAN_B 512
#define NBLK ((NN + SCAN_B - 1) / SCAN_B)   // 98

// GEMM tiling
#define BM 64
#define LDA 40                     // 32 + 8 skew
#define LDW 136                    // 128 + 8 skew
#define SMEM_FLOATS 8704           // max(64*40 + 32*136, 64*136) = 8704

// ---------------- scratch (static device globals; no allocation) ----------------
__device__ int    g_is64;
__device__ int    g_counts[NN];
__device__ int    g_fill[NN];
__device__ int    g_rowptr[NN + 1];
__device__ int    g_col[NE];
__device__ float  g_dinv[NN];
__device__ uint2  g_msg[NN * MQ];    // fp16 messages (dinv-scaled GEMM output)
__device__ float4 g_bufB[NN * FQ];   // layer input / agg output (fp32)
__device__ float  g_pool[NG * FF];
__device__ int    g_bsum[NBLK];

// bit reinterpretation helpers
__device__ __forceinline__ unsigned h2u(__half2 h) { return *reinterpret_cast<unsigned*>(&h); }
__device__ __forceinline__ __half2 u2h(unsigned u) { return *reinterpret_cast<__half2*>(&u); }

// dtype-agnostic index load (edge_index / batch may be int32 or int64)
__device__ __forceinline__ int load_idx(const void* p, long long i, int is64) {
    if (is64) return (int)((const long long*)p)[i];
    return ((const int*)p)[i];
}

// ---------------- init: zero counts + dtype detect ----------------
__global__ void k_init(const int* __restrict__ w32) {
    int i = blockIdx.x * blockDim.x + threadIdx.x;
    if (i < NN) { g_counts[i] = 0; g_fill[i] = 0; }
    if (i == 0) {
        int nz = 0;
        #pragma unroll
        for (int k = 0; k < 16; k++) nz |= w32[2 * k + 1];
        g_is64 = (nz == 0) ? 1 : 0;
    }
}

__global__ void k_count(const void* __restrict__ ei) {
    int i = blockIdx.x * blockDim.x + threadIdx.x;
    if (i >= NE) return;
    int d = load_idx(ei, (long long)NE + i, g_is64);
    atomicAdd(&g_counts[d], 1);
}

// block-wide inclusive scan via shuffles; writes exclusive partials + block sums
__global__ void k_scan1() {
    __shared__ int warp_sums[SCAN_B / 32];
    int i = blockIdx.x * SCAN_B + threadIdx.x;
    int v = (i < NN) ? g_counts[i] : 0;
    int lane = threadIdx.x & 31;
    int wid  = threadIdx.x >> 5;

    int x = v;
    #pragma unroll
    for (int off = 1; off < 32; off <<= 1) {
        int t = __shfl_up_sync(0xffffffffu, x, off);
        if (lane >= off) x += t;
    }
    if (lane == 31) warp_sums[wid] = x;
    __syncthreads();
    if (wid == 0) {
        int w = (lane < SCAN_B / 32) ? warp_sums[lane] : 0;
        #pragma unroll
        for (int off = 1; off < SCAN_B / 32; off <<= 1) {
            int t = __shfl_up_sync(0xffffffffu, w, off);
            if (lane >= off) w += t;
        }
        if (lane < SCAN_B / 32) warp_sums[lane] = w;
    }
    __syncthreads();
    int base = (wid > 0) ? warp_sums[wid - 1] : 0;
    int incl = base + x;
    if (i < NN) g_rowptr[i] = incl - v;            // exclusive within block
    if (threadIdx.x == SCAN_B - 1) g_bsum[blockIdx.x] = incl;
}

// finalize rowptr: block b adds sum(bsum[0..b-1]); also compute dinv
__global__ void k_scan3() {
    __shared__ int s_off;
    int b = blockIdx.x;
    if (threadIdx.x < 32) {
        int acc = 0;
        for (int k = threadIdx.x; k < b; k += 32) acc += g_bsum[k];
        #pragma unroll
        for (int off = 16; off; off >>= 1) acc += __shfl_down_sync(0xffffffffu, acc, off);
        if (threadIdx.x == 0) s_off = acc;
    }
    __syncthreads();
    int i = b * SCAN_B + threadIdx.x;
    if (i < NN) {
        g_rowptr[i] += s_off;
        g_dinv[i] = rsqrtf((float)(g_counts[i] + 1));   // +1 = self loop
    }
    if (i == 0) g_rowptr[NN] = NE;
}

__global__ void k_fill(const void* __restrict__ ei) {
    int i = blockIdx.x * blockDim.x + threadIdx.x;
    if (i >= NE) return;
    int is64 = g_is64;
    int s = load_idx(ei, (long long)i, is64);
    int d = load_idx(ei, (long long)NE + i, is64);
    int pos = g_rowptr[d] + atomicAdd(&g_fill[d], 1);
    g_col[pos] = s;
}

// ---------------- GEMM (tf32): g_msg[r] = fp16( (src[r] @ W) * dinv[r] ) ----------------
__global__ void __launch_bounds__(256) k_gemm(const float* __restrict__ xext,
                                              int srcSel,
                                              const float* __restrict__ W) {
    __shared__ float sm[SMEM_FLOATS];
    float* As = sm;               // 64 x LDA
    float* Ws = sm + BM * LDA;    // 32 x LDW

    const bool useX = (srcSel == 0);
    int tid = threadIdx.x;
    int wid = tid >> 5;
    int stripe = wid >> 1;        // 0..3 (16-row stripe)
    int half   = wid & 1;         // 0..1 (64-col half)
    int rowBase = blockIdx.x * BM;

    wmma::fragment<wmma::accumulator, 16, 16, 8, float> acc[4];
    #pragma unroll
    for (int c = 0; c < 4; c++) wmma::fill_fragment(acc[c], 0.0f);

    for (int kc = 0; kc < 4; kc++) {              // K chunks of 32
        #pragma unroll
        for (int t = 0; t < 2; t++) {
            int idx = tid + t * 256;
            int r   = idx >> 3;
            int kq  = idx & 7;
            int grow = rowBase + r;
            float4 v = make_float4(0.f, 0.f, 0.f, 0.f);
            if (grow < NN) {
                if (useX) v = *(const float4*)&xext[(long long)grow * FF + kc * 32 + kq * 4];
                else      v = g_bufB[grow * FQ + kc * 8 + kq];
            }
            float* dst = &As[r * LDA + kq * 4];
            dst[0] = wmma::__float_to_tf32(v.x);
            dst[1] = wmma::__float_to_tf32(v.y);
            dst[2] = wmma::__float_to_tf32(v.z);
            dst[3] = wmma::__float_to_tf32(v.w);
        }
        #pragma unroll
        for (int t = 0; t < 4; t++) {
            int idx = tid + t * 256;
            int k   = idx >> 5;
            int cq  = idx & 31;
            float4 v = *(const float4*)&W[(kc * 32 + k) * FF + cq * 4];
            float* dst = &Ws[k * LDW + cq * 4];
            dst[0] = wmma::__float_to_tf32(v.x);
            dst[1] = wmma::__float_to_tf32(v.y);
            dst[2] = wmma::__float_to_tf32(v.z);
            dst[3] = wmma::__float_to_tf32(v.w);
        }
        __syncthreads();

        #pragma unroll
        for (int kk = 0; kk < 4; kk++) {
            wmma::fragment<wmma::matrix_a, 16, 16, 8, wmma::precision::tf32, wmma::row_major> a;
            wmma::load_matrix_sync(a, &As[stripe * 16 * LDA + kk * 8], LDA);
            #pragma unroll
            for (int c = 0; c < 4; c++) {
                wmma::fragment<wmma::matrix_b, 16, 16, 8, wmma::precision::tf32, wmma::row_major> b;
                wmma::load_matrix_sync(b, &Ws[kk * 8 * LDW + half * 64 + c * 16], LDW);
                wmma::mma_sync(acc[c], a, b, acc[c]);
            }
        }
        __syncthreads();
    }

    // epilogue: frags -> shared -> dinv scale -> fp16 -> global
    float* Cs = sm;               // 64 x LDW
    #pragma unroll
    for (int c = 0; c < 4; c++)
        wmma::store_matrix_sync(&Cs[(stripe * 16) * LDW + half * 64 + c * 16],
                                acc[c], LDW, wmma::mem_row_major);
    __syncthreads();

    #pragma unroll
    for (int t = 0; t < 8; t++) {
        int idx = tid + t * 256;          // 64 rows x 32 quads
        int r = idx >> 5;
        int q = idx & 31;
        int grow = rowBase + r;
        if (grow < NN) {
            float dv = g_dinv[grow];
            float4 v = *(float4*)&Cs[r * LDW + q * 4];
            __half2 h0 = __floats2half2_rn(v.x * dv, v.y * dv);
            __half2 h1 = __floats2half2_rn(v.z * dv, v.w * dv);
            uint2 u;
            u.x = h2u(h0);
            u.y = h2u(h1);
            g_msg[grow * MQ + q] = u;
        }
    }
}

// ---------------- aggregation: bufB[v] = act( dinv[v]*sum_{u in N(v)+v} msg[u] + b ) ----
// shuffle-prefetch of neighbor ids; 4 independent gathers in flight, 2 acc chains.
__device__ __forceinline__ void acc_msg(float4& a, uint2 m) {
    float2 lo = __half22float2(u2h(m.x));
    float2 hi = __half22float2(u2h(m.y));
    a.x += lo.x; a.y += lo.y; a.z += hi.x; a.w += hi.y;
}

__global__ void __launch_bounds__(256) k_agg(const float* __restrict__ bias,
                                             int do_relu) {
    int v    = (blockIdx.x * blockDim.x + threadIdx.x) >> 5;  // one warp per node
    int lane = threadIdx.x & 31;
    if (v >= NN) return;

    float4 acc0 = make_float4(0.f, 0.f, 0.f, 0.f);
    float4 acc1 = make_float4(0.f, 0.f, 0.f, 0.f);
    acc_msg(acc0, g_msg[v * MQ + lane]);                       // self loop

    int s = g_rowptr[v];
    int deg = g_rowptr[v + 1] - s;

    for (int base = 0; base < deg; base += 32) {
        int rem = deg - base;
        int n = rem < 32 ? rem : 32;
        int myc = 0;
        if (lane < n) myc = g_col[s + base + lane];            // coalesced prefetch

        int jj = 0;
        for (; jj + 4 <= n; jj += 4) {
            int u0 = __shfl_sync(0xffffffffu, myc, jj);
            int u1 = __shfl_sync(0xffffffffu, myc, jj + 1);
            int u2 = __shfl_sync(0xffffffffu, myc, jj + 2);
            int u3 = __shfl_sync(0xffffffffu, myc, jj + 3);
            uint2 m0 = g_msg[u0 * MQ + lane];
            uint2 m1 = g_msg[u1 * MQ + lane];
            uint2 m2 = g_msg[u2 * MQ + lane];
            uint2 m3 = g_msg[u3 * MQ + lane];
            acc_msg(acc0, m0);
            acc_msg(acc1, m1);
            acc_msg(acc0, m2);
            acc_msg(acc1, m3);
        }
        for (; jj < n; jj++) {
            int u = __shfl_sync(0xffffffffu, myc, jj);
            acc_msg(acc0, g_msg[u * MQ + lane]);
        }
    }

    float  dv = g_dinv[v];
    float4 b  = *(const float4*)&bias[lane * 4];
    float4 acc;
    acc.x = (acc0.x + acc1.x) * dv + b.x;
    acc.y = (acc0.y + acc1.y) * dv + b.y;
    acc.z = (acc0.z + acc1.z) * dv + b.z;
    acc.w = (acc0.w + acc1.w) * dv + b.w;
    if (do_relu) {
        acc.x = fmaxf(acc.x, 0.f); acc.y = fmaxf(acc.y, 0.f);
        acc.z = fmaxf(acc.z, 0.f); acc.w = fmaxf(acc.w, 0.f);
    }
    g_bufB[v * FQ + lane] = acc;
}

// ---------------- mean pooling per graph (batch sorted); reads g_bufB ----------------
__device__ __forceinline__ int lower_bound_idx(const void* a, int val, int is64) {
    int lo = 0, hi = NN;
    while (lo < hi) {
        int mid = (lo + hi) >> 1;
        if (load_idx(a, mid, is64) < val) lo = mid + 1; else hi = mid;
    }
    return lo;
}

__global__ void __launch_bounds__(1024) k_pool(const void* __restrict__ batch) {
    __shared__ int se[2];
    __shared__ float red[8][FF];
    int g = blockIdx.x;
    if (threadIdx.x == 0) {
        int is64 = g_is64;
        se[0] = lower_bound_idx(batch, g, is64);
        se[1] = lower_bound_idx(batch, g + 1, is64);
    }
    __syncthreads();
    int s = se[0], e = se[1];
    int col = threadIdx.x & 127;
    int rc  = threadIdx.x >> 7;        // 0..7 row chunk
    const float* h = (const float*)g_bufB;
    float sum = 0.f;
    for (int i = s + rc; i < e; i += 8) sum += h[i * FF + col];
    red[rc][col] = sum;
    __syncthreads();
    if (rc == 0) {
        float t = 0.f;
        #pragma unroll
        for (int k = 0; k < 8; k++) t += red[k][col];
        float cnt = (float)(e - s);
        g_pool[g * FF + col] = t / fmaxf(cnt, 1.0f);
    }
}

// ---------------- classifier ----------------
__global__ void k_cls(const float* __restrict__ Wc,
                      const float* __restrict__ bc,
                      float* __restrict__ out) {
    int tid = threadIdx.x;             // 1024 threads
    int g = tid >> 4;
    int c = tid & 15;
    float sum = bc[c];
    #pragma unroll 8
    for (int k = 0; k < FF; k++)
        sum += g_pool[g * FF + k] * Wc[k * NC + c];
    out[g * NC + c] = sum;
}

// ---------------- launch ----------------
extern "C" void kernel_launch(void* const* d_in, const int* in_sizes, int n_in,
                              void* d_out, int out_size) {
    const float* x  = (const float*)d_in[0];
    const void*  ei = d_in[1];
    const void*  batch = d_in[2];
    const float* W0 = (const float*)d_in[3];
    const float* b0 = (const float*)d_in[4];
    const float* W1 = (const float*)d_in[5];
    const float* b1 = (const float*)d_in[6];
    const float* W2 = (const float*)d_in[7];
    const float* b2 = (const float*)d_in[8];
    const float* Wc = (const float*)d_in[9];
    const float* bc = (const float*)d_in[10];
    float* out = (float*)d_out;

    k_init <<<(NN + 255) / 256, 256>>>((const int*)ei);
    k_count<<<(NE + 255) / 256, 256>>>(ei);
    k_scan1<<<NBLK, SCAN_B>>>();
    k_scan3<<<NBLK, SCAN_B>>>();
    k_fill <<<(NE + 255) / 256, 256>>>(ei);

    const int gemm_grid = (NN + BM - 1) / BM;
    const int agg_grid  = (NN + 7) / 8;

    k_gemm<<<gemm_grid, 256>>>(x, 0, W0);
    k_agg <<<agg_grid,  256>>>(b0, 1);
    k_gemm<<<gemm_grid, 256>>>(x, 1, W1);
    k_agg <<<agg_grid,  256>>>(b1, 1);
    k_gemm<<<gemm_grid, 256>>>(x, 1, W2);
    k_agg <<<agg_grid,  256>>>(b2, 0);

    k_pool<<<NG, 1024>>>(batch);
    k_cls <<<1, 1024>>>(Wc, bc, out);
}